// round 2
// baseline (speedup 1.0000x reference)
#include <cuda_runtime.h>
#include <cstdint>

#define NN   100000
#define NE   1600000
#define DIN  512
#define HD   128
#define DOUT 64

// ---------------- scratch (device globals: allocation-free) ----------------
__device__ float g_deg[NN];                      // degree, then dinv in-place
__device__ float g_h0 [(size_t)NN * HD];         // relu(x@w1+b1)
__device__ float g_h  [(size_t)NN * HD];         // layer output
__device__ float g_agg[(size_t)NN * HD];         // aggregation buffer

// ---------------- degree / dinv ----------------
__global__ void deg_init_kernel() {
    int i = blockIdx.x * blockDim.x + threadIdx.x;
    if (i < NN) g_deg[i] = 1.0f;                 // self-loop
}

__global__ void deg_accum_kernel(const int* __restrict__ ei) {
    int e = blockIdx.x * blockDim.x + threadIdx.x;
    if (e < NE) atomicAdd(&g_deg[ei[NE + e]], 1.0f);   // col = target
}

__global__ void dinv_kernel() {
    int i = blockIdx.x * blockDim.x + threadIdx.x;
    if (i < NN) g_deg[i] = rsqrtf(g_deg[i]);     // deg >= 1 always
}

// ---------------- self-loop init: agg[i] = dinv[i]^2 * h[i] ----------------
__global__ void selfloop_kernel(const float* __restrict__ src) {
    int idx = blockIdx.x * blockDim.x + threadIdx.x;   // over NN * (HD/4)
    if (idx >= NN * (HD / 4)) return;
    int node = idx >> 5;           // HD/4 = 32
    int f    = idx & 31;
    float d = g_deg[node];
    float w = d * d;
    float4 v = ((const float4*)(src + (size_t)node * HD))[f];
    v.x *= w; v.y *= w; v.z *= w; v.w *= w;
    ((float4*)(g_agg + (size_t)node * HD))[f] = v;
}

// ---------------- edge aggregation: warp per edge, float4 per lane ----------
__global__ void edge_kernel(const int* __restrict__ ei, const float* __restrict__ src) {
    int gid  = blockIdx.x * blockDim.x + threadIdx.x;
    int e    = gid >> 5;
    if (e >= NE) return;
    int lane = gid & 31;
    int r = __ldg(&ei[e]);         // source
    int c = __ldg(&ei[NE + e]);    // target
    float w = g_deg[r] * g_deg[c];
    float4 v = ((const float4*)(src + (size_t)r * HD))[lane];
    v.x *= w; v.y *= w; v.z *= w; v.w *= w;
    float4* dst = ((float4*)(g_agg + (size_t)c * HD)) + lane;
    asm volatile("red.global.add.v4.f32 [%0], {%1, %2, %3, %4};"
                 :: "l"(__cvta_generic_to_global(dst)),
                    "f"(v.x), "f"(v.y), "f"(v.z), "f"(v.w)
                 : "memory");
}

// ---------------- fp32 tiled GEMM, C[M,BN] = op(A)[M,K] @ B[K,BN] ----------
// COMBINE: A_eff = ca*A + cb*A2 (residual fold). Grid is 1D over M (BN == full N).
template<int BN, int TN, bool RELU, bool BIAS, bool COMBINE>
__global__ void __launch_bounds__(256, 2)
gemm_kernel(const float* __restrict__ A, const float* __restrict__ A2,
            const float* __restrict__ B, const float* __restrict__ bias,
            float* __restrict__ C, int M, int K, float ca, float cb)
{
    constexpr int BM = 128, BK = 16, TM = 8;
    __shared__ float As[BK][BM];
    __shared__ float Bs[BK][BN];

    const int tid = threadIdx.x;
    const int tx  = tid % (BN / TN);        // 0..15
    const int ty  = tid / (BN / TN);        // 0..15
    const int blockM = blockIdx.x * BM;

    float acc[TM][TN];
    #pragma unroll
    for (int i = 0; i < TM; i++)
        #pragma unroll
        for (int j = 0; j < TN; j++) acc[i][j] = 0.0f;

    constexpr int A_ITER = (BM * BK / 4) / 256;      // 2
    constexpr int B_ITER = (BK * BN / 4 + 255) / 256; // 2 (BN=128) or 1 (BN=64)

    for (int k0 = 0; k0 < K; k0 += BK) {
        // A tile: [BM x BK], stored transposed As[k][m]
        #pragma unroll
        for (int it = 0; it < A_ITER; it++) {
            int id  = tid + it * 256;
            int m   = id >> 2;              // BK/4 = 4 float4 per row
            int k4  = id & 3;
            int row = blockM + m;
            float4 v = make_float4(0.f, 0.f, 0.f, 0.f);
            if (row < M) {
                v = *(const float4*)(A + (size_t)row * K + k0 + k4 * 4);
                if (COMBINE) {
                    float4 v2 = *(const float4*)(A2 + (size_t)row * K + k0 + k4 * 4);
                    v.x = ca * v.x + cb * v2.x;
                    v.y = ca * v.y + cb * v2.y;
                    v.z = ca * v.z + cb * v2.z;
                    v.w = ca * v.w + cb * v2.w;
                }
            }
            As[k4 * 4 + 0][m] = v.x;
            As[k4 * 4 + 1][m] = v.y;
            As[k4 * 4 + 2][m] = v.z;
            As[k4 * 4 + 3][m] = v.w;
        }
        // B tile: [BK x BN] row-major (B stride == BN for all our weights)
        #pragma unroll
        for (int it = 0; it < B_ITER; it++) {
            int id = tid + it * 256;
            if ((BK * BN / 4) % 256 == 0 || id < BK * BN / 4) {
                int kb = id / (BN / 4);
                int n4 = id % (BN / 4);
                float4 v = *(const float4*)(B + (size_t)(k0 + kb) * BN + n4 * 4);
                *(float4*)&Bs[kb][n4 * 4] = v;
            }
        }
        __syncthreads();

        #pragma unroll
        for (int k = 0; k < BK; k++) {
            float a[TM], b[TN];
            #pragma unroll
            for (int i = 0; i < TM; i++) a[i] = As[k][ty * TM + i];
            #pragma unroll
            for (int j = 0; j < TN; j++) b[j] = Bs[k][tx * TN + j];
            #pragma unroll
            for (int i = 0; i < TM; i++)
                #pragma unroll
                for (int j = 0; j < TN; j++) acc[i][j] += a[i] * b[j];
        }
        __syncthreads();
    }

    // epilogue: float4 stores
    #pragma unroll
    for (int i = 0; i < TM; i++) {
        int row = blockM + ty * TM + i;
        if (row >= M) continue;
        #pragma unroll
        for (int j4 = 0; j4 < TN / 4; j4++) {
            int col = tx * TN + j4 * 4;
            float4 v;
            v.x = acc[i][j4 * 4 + 0];
            v.y = acc[i][j4 * 4 + 1];
            v.z = acc[i][j4 * 4 + 2];
            v.w = acc[i][j4 * 4 + 3];
            if (BIAS) {
                v.x += bias[col + 0]; v.y += bias[col + 1];
                v.z += bias[col + 2]; v.w += bias[col + 3];
            }
            if (RELU) {
                v.x = fmaxf(v.x, 0.f); v.y = fmaxf(v.y, 0.f);
                v.z = fmaxf(v.z, 0.f); v.w = fmaxf(v.w, 0.f);
            }
            *(float4*)(C + (size_t)row * BN + col) = v;
        }
    }
}

// ---------------- launch ----------------
extern "C" void kernel_launch(void* const* d_in, const int* in_sizes, int n_in,
                              void* d_out, int out_size)
{
    const float* x  = (const float*)d_in[0];
    const int*   ei = (const int*)  d_in[1];
    const float* w1 = (const float*)d_in[2];
    const float* b1 = (const float*)d_in[3];
    const float* cw = (const float*)d_in[4];   // [2,128,128]
    const float* w2 = (const float*)d_in[5];
    const float* b2 = (const float*)d_in[6];

    float* out    = (float*)d_out;
    float* hout   = out;                       // [NN, 128]
    float* logits = out + (size_t)NN * HD;     // [NN, 64]

    float *p_h0, *p_h, *p_agg;
    cudaGetSymbolAddress((void**)&p_h0,  g_h0);
    cudaGetSymbolAddress((void**)&p_h,   g_h);
    cudaGetSymbolAddress((void**)&p_agg, g_agg);

    const int TPB = 256;
    const int gemm_grid = (NN + 127) / 128;

    // degrees -> dinv (in place)
    deg_init_kernel <<<(NN + TPB - 1) / TPB, TPB>>>();
    deg_accum_kernel<<<(NE + TPB - 1) / TPB, TPB>>>(ei);
    dinv_kernel     <<<(NN + TPB - 1) / TPB, TPB>>>();

    // h0 = relu(x @ w1 + b1)
    gemm_kernel<128, 8, true, true, false><<<gemm_grid, TPB>>>(
        x, nullptr, w1, b1, p_h0, NN, DIN, 0.f, 0.f);

    // ---- layer 1: agg(h0) -> h = (0.9*agg + 0.1*h0) @ cw[0]
    selfloop_kernel<<<(NN * 32 + TPB - 1) / TPB, TPB>>>(p_h0);
    edge_kernel    <<<NE / 8, TPB>>>(ei, p_h0);
    gemm_kernel<128, 8, false, false, true><<<gemm_grid, TPB>>>(
        p_agg, p_h0, cw, nullptr, p_h, NN, HD, 0.9f, 0.1f);

    // ---- layer 2: agg(h) -> hout = (0.9*agg + 0.1*h0) @ cw[1]  (directly to d_out)
    selfloop_kernel<<<(NN * 32 + TPB - 1) / TPB, TPB>>>(p_h);
    edge_kernel    <<<NE / 8, TPB>>>(ei, p_h);
    gemm_kernel<128, 8, false, false, true><<<gemm_grid, TPB>>>(
        p_agg, p_h0, cw + HD * HD, nullptr, hout, NN, HD, 0.9f, 0.1f);

    // logits = hout @ w2 + b2
    gemm_kernel<64, 4, false, true, false><<<gemm_grid, TPB>>>(
        hout, nullptr, w2, b2, logits, NN, HD, 0.f, 0.f);
}